// round 1
// baseline (speedup 1.0000x reference)
#include <cuda_runtime.h>
#include <cuda_bf16.h>
#include <cstdint>
#include <math_constants.h>

// Problem constants
#define B 32
#define SP 8192
#define D 2048
#define H 16
#define KVH 2
#define DH 128
#define NQKV 2560           // 2048 (q) + 256 (k) + 256 (v)
#define SCALE 0.08838834764831845f  // 1/sqrt(128)

// GEMM tiling
#define DCHUNK 256
#define NCHUNK 8            // D / DCHUNK

// Attention tiling
#define TS 32               // positions per tile
#define NSPLIT 8
#define SCHUNK 1024         // SP / NSPLIT
#define NTILES 32           // SCHUNK / TS
#define ATTN_SMEM_BYTES ((4*TS*DH + TS*9 + 8) * 4)

// Scratch (device globals; no allocation allowed)
__device__ float g_qkv_part[NCHUNK * B * NQKV];
__device__ float g_qkv[B * NQKV];
__device__ float g_pacc[B * KVH * NSPLIT * 8 * DH];
__device__ float g_pm[B * KVH * NSPLIT * 8];
__device__ float g_pl[B * KVH * NSPLIT * 8];
__device__ float g_attn[B * H * DH];
__device__ float g_opart[NCHUNK * B * D];

__device__ __forceinline__ float warp_sum(float v) {
#pragma unroll
    for (int o = 16; o; o >>= 1) v += __shfl_xor_sync(0xffffffffu, v, o);
    return v;
}
__device__ __forceinline__ float warp_max(float v) {
#pragma unroll
    for (int o = 16; o; o >>= 1) v = fmaxf(v, __shfl_xor_sync(0xffffffffu, v, o));
    return v;
}

// ---------------------------------------------------------------------------
// Fused QKV partial GEMM: X[32,2048] @ {Wq|Wk|Wv} -> partial sums per D-chunk.
// grid (20, 8), block 256. Each CTA: 128 output cols x 32 batches x 256 D.
// ---------------------------------------------------------------------------
__global__ __launch_bounds__(256) void qkv_partial_kernel(
    const float* __restrict__ X,
    const float* __restrict__ Wq, const float* __restrict__ Wk,
    const float* __restrict__ Wv)
{
    __shared__ float xs[DCHUNK * 36];   // transposed X tile, padded
    int t = threadIdx.x;
    int d0 = blockIdx.y * DCHUNK;

#pragma unroll
    for (int i = 0; i < B; i++)
        xs[t * 36 + i] = X[i * D + d0 + t];
    __syncthreads();

    int colbase = blockIdx.x * 128;
    const float* W; int Nw, lc;
    if (colbase < 2048)       { W = Wq; Nw = 2048; lc = colbase; }
    else if (colbase < 2304)  { W = Wk; Nw = 256;  lc = colbase - 2048; }
    else                      { W = Wv; Nw = 256;  lc = colbase - 2304; }

    int cg = t & 31;   // col group (4 cols each)
    int bg = t >> 5;   // batch group (4 batches each)

    const float* wp = W + (size_t)d0 * Nw + lc + cg * 4;
    float a00=0,a01=0,a02=0,a03=0, a10=0,a11=0,a12=0,a13=0;
    float a20=0,a21=0,a22=0,a23=0, a30=0,a31=0,a32=0,a33=0;

#pragma unroll 4
    for (int dd = 0; dd < DCHUNK; dd++) {
        float4 w4 = *(const float4*)wp; wp += Nw;
        float4 x4 = *(const float4*)(xs + dd * 36 + bg * 4);
        a00 += x4.x*w4.x; a01 += x4.x*w4.y; a02 += x4.x*w4.z; a03 += x4.x*w4.w;
        a10 += x4.y*w4.x; a11 += x4.y*w4.y; a12 += x4.y*w4.z; a13 += x4.y*w4.w;
        a20 += x4.z*w4.x; a21 += x4.z*w4.y; a22 += x4.z*w4.z; a23 += x4.z*w4.w;
        a30 += x4.w*w4.x; a31 += x4.w*w4.y; a32 += x4.w*w4.z; a33 += x4.w*w4.w;
    }

    float* o = g_qkv_part + ((size_t)blockIdx.y * B) * NQKV + colbase + cg * 4;
    *(float4*)(o + (size_t)(bg*4+0) * NQKV) = make_float4(a00,a01,a02,a03);
    *(float4*)(o + (size_t)(bg*4+1) * NQKV) = make_float4(a10,a11,a12,a13);
    *(float4*)(o + (size_t)(bg*4+2) * NQKV) = make_float4(a20,a21,a22,a23);
    *(float4*)(o + (size_t)(bg*4+3) * NQKV) = make_float4(a30,a31,a32,a33);
}

// Reduce chunks + bias -> g_qkv. grid 320, block 256.
__global__ void qkv_reduce_kernel(const float* __restrict__ bq,
                                  const float* __restrict__ bk,
                                  const float* __restrict__ bv)
{
    int idx = blockIdx.x * 256 + threadIdx.x;
    int b = idx / NQKV, c = idx % NQKV;
    float s;
    if (c < 2048) s = bq[c];
    else if (c < 2304) s = bk[c - 2048];
    else s = bv[c - 2304];
#pragma unroll
    for (int ch = 0; ch < NCHUNK; ch++)
        s += g_qkv_part[((size_t)ch * B + b) * NQKV + c];
    g_qkv[idx] = s;
}

// RoPE in-place on q (16 heads) and k (2 heads). grid (18, 32), block 128.
__global__ void rope_kernel(const float* __restrict__ cosp,
                            const float* __restrict__ sinp)
{
    int hs = blockIdx.x, b = blockIdx.y, d = threadIdx.x;
    int base = (hs < H) ? hs * DH : 2048 + (hs - H) * DH;
    float* p = g_qkv + b * NQKV + base;
    float x  = p[d];
    float xp = p[(d + 64) & 127];
    float rot = (d < 64) ? -xp : xp;
    __syncthreads();
    p[d] = x * cosp[b * DH + d] + rot * sinp[b * DH + d];
}

// ---------------------------------------------------------------------------
// Split-KV flash-decode over the 8192 past positions (new token folded into
// the combine kernel -> no masking here). grid (8, 2, 32), block 256.
// Warp-per-position score phase (q in regs, KV read once from smem),
// warp-per-head softmax, warp-per-position V with distributed accumulators.
// ---------------------------------------------------------------------------
__global__ __launch_bounds__(256, 2) void attn_split_kernel(
    const float* __restrict__ past_k, const float* __restrict__ past_v)
{
    extern __shared__ float sm[];
    float* k_sm = sm;                    // [2][TS*DH]
    float* v_sm = sm + 2 * TS * DH;      // [2][TS*DH]
    float* sp   = sm + 4 * TS * DH;      // [TS][9] scores/probs (padded)
    float* f_sm = sp + TS * 9;           // [8] per-head rescale factors

    int split = blockIdx.x, kv = blockIdx.y, b = blockIdx.z;
    int t = threadIdx.x, w = t >> 5, l = t & 31;

    // q fragments: lane l holds q[h][l*4 .. l*4+3] * scale for all 8 heads
    float q_reg[8][4];
#pragma unroll
    for (int h = 0; h < 8; h++) {
        float4 q4 = *(const float4*)(g_qkv + b * NQKV + (kv * 8 + h) * DH + l * 4);
        q_reg[h][0] = q4.x * SCALE; q_reg[h][1] = q4.y * SCALE;
        q_reg[h][2] = q4.z * SCALE; q_reg[h][3] = q4.w * SCALE;
    }
    float m_run = -CUDART_INF_F, l_run = 0.f;
    float acc[8][4] = {};

    const float* kbase = past_k + ((size_t)(b * KVH + kv) * SP + (size_t)split * SCHUNK) * DH;
    const float* vbase = past_v + ((size_t)(b * KVH + kv) * SP + (size_t)split * SCHUNK) * DH;

    uint32_t k_u32 = (uint32_t)__cvta_generic_to_shared(k_sm);
    uint32_t v_u32 = (uint32_t)__cvta_generic_to_shared(v_sm);
    int r = t >> 3, c = t & 7;

    auto load_tile = [&](int stage, int tile) {
        const float* kp = kbase + (size_t)tile * TS * DH;
        const float* vp = vbase + (size_t)tile * TS * DH;
        uint32_t ks = k_u32 + stage * TS * DH * 4;
        uint32_t vs = v_u32 + stage * TS * DH * 4;
#pragma unroll
        for (int ii = 0; ii < 4; ii++) {
            int off = r * DH + (c + ii * 8) * 4;
            asm volatile("cp.async.cg.shared.global [%0], [%1], 16;\n"
                         :: "r"(ks + off * 4), "l"(kp + off));
            asm volatile("cp.async.cg.shared.global [%0], [%1], 16;\n"
                         :: "r"(vs + off * 4), "l"(vp + off));
        }
        asm volatile("cp.async.commit_group;\n");
    };

    load_tile(0, 0);
    for (int tile = 0; tile < NTILES; tile++) {
        int cur = tile & 1;
        if (tile + 1 < NTILES) {
            load_tile(cur ^ 1, tile + 1);
            asm volatile("cp.async.wait_group 1;\n");
        } else {
            asm volatile("cp.async.wait_group 0;\n");
        }
        __syncthreads();

        const float* kc = k_sm + cur * TS * DH;
        const float* vc = v_sm + cur * TS * DH;

        // scores: warp w handles positions w*4 .. w*4+3, all 8 heads
#pragma unroll
        for (int jj = 0; jj < 4; jj++) {
            int j = w * 4 + jj;
            float4 kf = *(const float4*)(kc + j * DH + l * 4);
#pragma unroll
            for (int h = 0; h < 8; h++) {
                float s = q_reg[h][0]*kf.x + q_reg[h][1]*kf.y
                        + q_reg[h][2]*kf.z + q_reg[h][3]*kf.w;
                s = warp_sum(s);
                if (l == h) sp[j * 9 + h] = s;
            }
        }
        __syncthreads();

        // online softmax: warp w owns head w (lane = position)
        {
            float sj = sp[l * 9 + w];
            float tm = warp_max(sj);
            float mn = fmaxf(m_run, tm);
            float p  = __expf(sj - mn);
            float su = warp_sum(p);
            float f  = __expf(m_run - mn);
            l_run = l_run * f + su;
            m_run = mn;
            sp[l * 9 + w] = p;
            if (l == 0) f_sm[w] = f;
        }
        __syncthreads();

        // V accumulation: warp w handles its 4 positions, all heads
#pragma unroll
        for (int h = 0; h < 8; h++) {
            float f = f_sm[h];
            acc[h][0] *= f; acc[h][1] *= f; acc[h][2] *= f; acc[h][3] *= f;
        }
#pragma unroll
        for (int jj = 0; jj < 4; jj++) {
            int j = w * 4 + jj;
            float4 vf = *(const float4*)(vc + j * DH + l * 4);
#pragma unroll
            for (int h = 0; h < 8; h++) {
                float p = sp[j * 9 + h];
                acc[h][0] += p * vf.x; acc[h][1] += p * vf.y;
                acc[h][2] += p * vf.z; acc[h][3] += p * vf.w;
            }
        }
        __syncthreads();
    }

    // combine per-warp partial accumulators (reuse k_sm: 8192 floats)
    float* st = k_sm;
#pragma unroll
    for (int h = 0; h < 8; h++)
        *(float4*)(st + w * 1024 + h * DH + l * 4) =
            make_float4(acc[h][0], acc[h][1], acc[h][2], acc[h][3]);
    __syncthreads();

    int pbase = ((b * KVH + kv) * NSPLIT + split) * 8;
#pragma unroll
    for (int it = 0; it < 4; it++) {
        int d = it * 32 + l;
        float s = 0.f;
#pragma unroll
        for (int ww = 0; ww < 8; ww++) s += st[ww * 1024 + w * DH + d];
        g_pacc[(size_t)(pbase + w) * DH + d] = s;
    }
    if (l == 0) { g_pm[pbase + w] = m_run; g_pl[pbase + w] = l_run; }
}

// Combine splits + fold in the single NEW token (q.k_new, v_new).
// grid (16, 32), block 128.
__global__ void combine_kernel()
{
    int h = blockIdx.x, b = blockIdx.y, d = threadIdx.x;
    int kv = h >> 3, hh = h & 7;

    float qd = g_qkv[b * NQKV + h * DH + d] * SCALE;
    float kn = g_qkv[b * NQKV + 2048 + kv * DH + d];
    float vn = g_qkv[b * NQKV + 2304 + kv * DH + d];

    __shared__ float red[4];
    float ws = warp_sum(qd * kn);
    if ((d & 31) == 0) red[d >> 5] = ws;
    __syncthreads();
    float s_new = red[0] + red[1] + red[2] + red[3];

    int base = ((b * KVH + kv) * NSPLIT) * 8 + hh;
    float ms[NSPLIT], ls[NSPLIT];
    float M = s_new;
#pragma unroll
    for (int s = 0; s < NSPLIT; s++) {
        ms[s] = g_pm[base + s * 8];
        ls[s] = g_pl[base + s * 8];
        M = fmaxf(M, ms[s]);
    }
    float en = __expf(s_new - M);
    float L = en;
    float o = en * vn;
#pragma unroll
    for (int s = 0; s < NSPLIT; s++) {
        float e = __expf(ms[s] - M);
        L += e * ls[s];
        o += e * g_pacc[(size_t)(((b * KVH + kv) * NSPLIT + s) * 8 + hh) * DH + d];
    }
    g_attn[b * (H * DH) + h * DH + d] = o / L;
}

// Output projection partial GEMM: g_attn[32,2048] @ Wo[2048,2048].
// grid (16, 8), block 256.
__global__ __launch_bounds__(256) void o_partial_kernel(const float* __restrict__ Wo)
{
    __shared__ float xs[DCHUNK * 36];
    int t = threadIdx.x;
    int d0 = blockIdx.y * DCHUNK;
#pragma unroll
    for (int i = 0; i < B; i++)
        xs[t * 36 + i] = g_attn[i * D + d0 + t];
    __syncthreads();

    int colbase = blockIdx.x * 128;
    int cg = t & 31, bg = t >> 5;
    const float* wp = Wo + (size_t)d0 * D + colbase + cg * 4;
    float a00=0,a01=0,a02=0,a03=0, a10=0,a11=0,a12=0,a13=0;
    float a20=0,a21=0,a22=0,a23=0, a30=0,a31=0,a32=0,a33=0;

#pragma unroll 4
    for (int dd = 0; dd < DCHUNK; dd++) {
        float4 w4 = *(const float4*)wp; wp += D;
        float4 x4 = *(const float4*)(xs + dd * 36 + bg * 4);
        a00 += x4.x*w4.x; a01 += x4.x*w4.y; a02 += x4.x*w4.z; a03 += x4.x*w4.w;
        a10 += x4.y*w4.x; a11 += x4.y*w4.y; a12 += x4.y*w4.z; a13 += x4.y*w4.w;
        a20 += x4.z*w4.x; a21 += x4.z*w4.y; a22 += x4.z*w4.z; a23 += x4.z*w4.w;
        a30 += x4.w*w4.x; a31 += x4.w*w4.y; a32 += x4.w*w4.z; a33 += x4.w*w4.w;
    }

    float* o = g_opart + ((size_t)blockIdx.y * B) * D + colbase + cg * 4;
    *(float4*)(o + (size_t)(bg*4+0) * D) = make_float4(a00,a01,a02,a03);
    *(float4*)(o + (size_t)(bg*4+1) * D) = make_float4(a10,a11,a12,a13);
    *(float4*)(o + (size_t)(bg*4+2) * D) = make_float4(a20,a21,a22,a23);
    *(float4*)(o + (size_t)(bg*4+3) * D) = make_float4(a30,a31,a32,a33);
}

// grid 256, block 256
__global__ void o_reduce_kernel(float* __restrict__ out)
{
    int idx = blockIdx.x * 256 + threadIdx.x;
    int b = idx / D, c = idx % D;
    float s = 0.f;
#pragma unroll
    for (int ch = 0; ch < NCHUNK; ch++)
        s += g_opart[((size_t)ch * B + b) * D + c];
    out[idx] = s;
}

extern "C" void kernel_launch(void* const* d_in, const int* in_sizes, int n_in,
                              void* d_out, int out_size)
{
    const float* hidden = (const float*)d_in[0];
    const float* cosp   = (const float*)d_in[1];
    const float* sinp   = (const float*)d_in[2];
    const float* past_k = (const float*)d_in[3];
    const float* past_v = (const float*)d_in[4];
    const float* Wq     = (const float*)d_in[5];
    const float* bq     = (const float*)d_in[6];
    const float* Wk     = (const float*)d_in[7];
    const float* bk     = (const float*)d_in[8];
    const float* Wv     = (const float*)d_in[9];
    const float* bv     = (const float*)d_in[10];
    const float* Wo     = (const float*)d_in[11];
    float* out = (float*)d_out;

    cudaFuncSetAttribute(attn_split_kernel,
                         cudaFuncAttributeMaxDynamicSharedMemorySize,
                         ATTN_SMEM_BYTES);

    qkv_partial_kernel<<<dim3(NQKV / 128, NCHUNK), 256>>>(hidden, Wq, Wk, Wv);
    qkv_reduce_kernel<<<(B * NQKV) / 256, 256>>>(bq, bk, bv);
    rope_kernel<<<dim3(H + KVH, B), 128>>>(cosp, sinp);
    attn_split_kernel<<<dim3(NSPLIT, KVH, B), 256, ATTN_SMEM_BYTES>>>(past_k, past_v);
    combine_kernel<<<dim3(H, B), 128>>>();
    o_partial_kernel<<<dim3(D / 128, NCHUNK), 256>>>(Wo);
    o_reduce_kernel<<<(B * D) / 256, 256>>>(out);
}

// round 2
// speedup vs baseline: 1.4357x; 1.4357x over previous
#include <cuda_runtime.h>
#include <cuda_bf16.h>
#include <cstdint>
#include <math_constants.h>

// Problem constants
#define B 32
#define SP 8192
#define D 2048
#define H 16
#define KVH 2
#define DH 128
#define NQKV 2560           // 2048 (q) + 256 (k) + 256 (v)
#define SCALE 0.08838834764831845f  // 1/sqrt(128)

// GEMM tiling
#define DCHUNK 128
#define NCHUNK 16           // D / DCHUNK

// Attention tiling
#define TS 32               // positions per tile
#define NSPLIT 8
#define SCHUNK 1024         // SP / NSPLIT
#define NTILES 32           // SCHUNK / TS
#define ATTN_SMEM_BYTES ((4*TS*DH + TS*9 + 8) * 4)

// Scratch (device globals; no allocation allowed)
__device__ float g_qkv_part[NCHUNK * B * NQKV];
__device__ float g_qkv[B * NQKV];
__device__ float g_pacc[B * KVH * NSPLIT * 8 * DH];
__device__ float g_pm[B * KVH * NSPLIT * 8];
__device__ float g_pl[B * KVH * NSPLIT * 8];
__device__ float g_attn[B * H * DH];
__device__ float g_opart[NCHUNK * B * D];

__device__ __forceinline__ float warp_sum(float v) {
#pragma unroll
    for (int o = 16; o; o >>= 1) v += __shfl_xor_sync(0xffffffffu, v, o);
    return v;
}
__device__ __forceinline__ float warp_max(float v) {
#pragma unroll
    for (int o = 16; o; o >>= 1) v = fmaxf(v, __shfl_xor_sync(0xffffffffu, v, o));
    return v;
}

// ---------------------------------------------------------------------------
// Fused QKV partial GEMM: X[32,2048] @ {Wq|Wk|Wv} -> partial sums per D-chunk.
// grid (40, 16), block 256. Each CTA: 64 output cols x 32 batches x 128 D.
// ---------------------------------------------------------------------------
__global__ __launch_bounds__(256) void qkv_partial_kernel(
    const float* __restrict__ X,
    const float* __restrict__ Wq, const float* __restrict__ Wk,
    const float* __restrict__ Wv)
{
    __shared__ float xs[DCHUNK * 33];
    int t = threadIdx.x;
    int d0 = blockIdx.y * DCHUNK;

#pragma unroll
    for (int k2 = 0; k2 < (DCHUNK * B) / 256; k2++) {
        int idx = t + k2 * 256;
        int d = idx & (DCHUNK - 1), bb = idx >> 7;
        xs[d * 33 + bb] = X[bb * D + d0 + d];
    }
    __syncthreads();

    int colbase = blockIdx.x * 64;
    const float* W; int Nw, lc;
    if (colbase < 2048)       { W = Wq; Nw = 2048; lc = colbase; }
    else if (colbase < 2304)  { W = Wk; Nw = 256;  lc = colbase - 2048; }
    else                      { W = Wv; Nw = 256;  lc = colbase - 2304; }

    int cg = t & 15;   // col group (4 cols)
    int bg = t >> 4;   // batch group (2 batches)

    const float* wp = W + (size_t)d0 * Nw + lc + cg * 4;
    float a00=0,a01=0,a02=0,a03=0, a10=0,a11=0,a12=0,a13=0;

#pragma unroll 4
    for (int dd = 0; dd < DCHUNK; dd++) {
        float4 w4 = *(const float4*)wp; wp += Nw;
        float x0 = xs[dd * 33 + bg * 2];
        float x1 = xs[dd * 33 + bg * 2 + 1];
        a00 += x0*w4.x; a01 += x0*w4.y; a02 += x0*w4.z; a03 += x0*w4.w;
        a10 += x1*w4.x; a11 += x1*w4.y; a12 += x1*w4.z; a13 += x1*w4.w;
    }

    float* o = g_qkv_part + ((size_t)blockIdx.y * B + bg * 2) * NQKV + colbase + cg * 4;
    *(float4*)o = make_float4(a00,a01,a02,a03);
    *(float4*)(o + NQKV) = make_float4(a10,a11,a12,a13);
}

// Fused: reduce 16 partial chunks + bias, then RoPE on q/k. grid 32, block 512.
__global__ void qkv_reduce_rope_kernel(const float* __restrict__ bq,
                                       const float* __restrict__ bk,
                                       const float* __restrict__ bv,
                                       const float* __restrict__ cosp,
                                       const float* __restrict__ sinp)
{
    __shared__ float buf[NQKV];
    int b = blockIdx.x, t = threadIdx.x;

    for (int c = t; c < NQKV; c += 512) {
        float s;
        if (c < 2048) s = bq[c];
        else if (c < 2304) s = bk[c - 2048];
        else s = bv[c - 2304];
#pragma unroll
        for (int ch = 0; ch < NCHUNK; ch++)
            s += g_qkv_part[((size_t)ch * B + b) * NQKV + c];
        buf[c] = s;
    }
    __syncthreads();

    for (int c = t; c < NQKV; c += 512) {
        float v = buf[c];
        if (c < 2304) {  // q or k head -> RoPE
            int d = c & 127;
            int base = c - d;
            float xp = buf[base + ((d + 64) & 127)];
            float rot = (d < 64) ? -xp : xp;
            v = v * cosp[b * DH + d] + rot * sinp[b * DH + d];
        }
        g_qkv[b * NQKV + c] = v;
    }
}

// ---------------------------------------------------------------------------
// Split-KV flash-decode. grid (8, 2, 32), block 256.
// Score phase: lane = (head, quarter) -> 32 FMA + 2 shfl per (pos, 8 heads).
// ---------------------------------------------------------------------------
__global__ __launch_bounds__(256, 2) void attn_split_kernel(
    const float* __restrict__ past_k, const float* __restrict__ past_v)
{
    extern __shared__ float sm[];
    float* k_sm = sm;                    // [2][TS*DH]
    float* v_sm = sm + 2 * TS * DH;      // [2][TS*DH]
    float* sp   = sm + 4 * TS * DH;      // [TS][9] scores/probs (padded)
    float* f_sm = sp + TS * 9;           // [8] per-head rescale factors

    int split = blockIdx.x, kv = blockIdx.y, b = blockIdx.z;
    int t = threadIdx.x, w = t >> 5, l = t & 31;
    int h = l >> 2, p = l & 3;           // score-phase lane mapping

    // q fragment: lane holds q[h][p*32 .. p*32+31] * scale, rotation-permuted
    float4 qr[8];
    {
        const float* qp = g_qkv + b * NQKV + (kv * 8 + h) * DH + p * 32;
#pragma unroll
        for (int i = 0; i < 8; i++) {
            int c = (i + 2 * p) & 7;
            float4 q4 = *(const float4*)(qp + c * 4);
            qr[i] = make_float4(q4.x * SCALE, q4.y * SCALE,
                                q4.z * SCALE, q4.w * SCALE);
        }
    }
    float m_run = -CUDART_INF_F, l_run = 0.f;
    float acc[8][4] = {};

    const float* kbase = past_k + ((size_t)(b * KVH + kv) * SP + (size_t)split * SCHUNK) * DH;
    const float* vbase = past_v + ((size_t)(b * KVH + kv) * SP + (size_t)split * SCHUNK) * DH;

    uint32_t k_u32 = (uint32_t)__cvta_generic_to_shared(k_sm);
    uint32_t v_u32 = (uint32_t)__cvta_generic_to_shared(v_sm);
    int r = t >> 3, c8 = t & 7;

    auto load_tile = [&](int stage, int tile) {
        const float* kp = kbase + (size_t)tile * TS * DH;
        const float* vp = vbase + (size_t)tile * TS * DH;
        uint32_t ks = k_u32 + stage * TS * DH * 4;
        uint32_t vs = v_u32 + stage * TS * DH * 4;
#pragma unroll
        for (int ii = 0; ii < 4; ii++) {
            int off = r * DH + (c8 + ii * 8) * 4;
            asm volatile("cp.async.cg.shared.global [%0], [%1], 16;\n"
                         :: "r"(ks + off * 4), "l"(kp + off));
            asm volatile("cp.async.cg.shared.global [%0], [%1], 16;\n"
                         :: "r"(vs + off * 4), "l"(vp + off));
        }
        asm volatile("cp.async.commit_group;\n");
    };

    load_tile(0, 0);
    for (int tile = 0; tile < NTILES; tile++) {
        int cur = tile & 1;
        if (tile + 1 < NTILES) {
            load_tile(cur ^ 1, tile + 1);
            asm volatile("cp.async.wait_group 1;\n");
        } else {
            asm volatile("cp.async.wait_group 0;\n");
        }
        __syncthreads();

        const float* kc = k_sm + cur * TS * DH;
        const float* vc = v_sm + cur * TS * DH;

        // scores: warp w -> positions w*4..w*4+3; lanes cover 8 heads x 4 quarters
#pragma unroll
        for (int jj = 0; jj < 4; jj++) {
            int j = w * 4 + jj;
            const float* kp = kc + j * DH + p * 32;
            float s0 = 0.f, s1 = 0.f, s2 = 0.f, s3 = 0.f;
#pragma unroll
            for (int i = 0; i < 8; i++) {
                int c = (i + 2 * p) & 7;
                float4 kf = *(const float4*)(kp + c * 4);
                s0 += qr[i].x * kf.x; s1 += qr[i].y * kf.y;
                s2 += qr[i].z * kf.z; s3 += qr[i].w * kf.w;
            }
            float s = (s0 + s1) + (s2 + s3);
            s += __shfl_xor_sync(0xffffffffu, s, 1);
            s += __shfl_xor_sync(0xffffffffu, s, 2);
            if (p == 0) sp[j * 9 + h] = s;
        }
        __syncthreads();

        // online softmax: warp w owns head w (lane = position)
        {
            float sj = sp[l * 9 + w];
            float tm = warp_max(sj);
            float mn = fmaxf(m_run, tm);
            float pw = __expf(sj - mn);
            float su = warp_sum(pw);
            float f  = __expf(m_run - mn);
            l_run = l_run * f + su;
            m_run = mn;
            sp[l * 9 + w] = pw;
            if (l == 0) f_sm[w] = f;
        }
        __syncthreads();

        // V accumulation: lane owns dims l*4..l*4+3 for all 8 heads
#pragma unroll
        for (int hh = 0; hh < 8; hh++) {
            float f = f_sm[hh];
            acc[hh][0] *= f; acc[hh][1] *= f; acc[hh][2] *= f; acc[hh][3] *= f;
        }
#pragma unroll
        for (int jj = 0; jj < 4; jj++) {
            int j = w * 4 + jj;
            float4 vf = *(const float4*)(vc + j * DH + l * 4);
#pragma unroll
            for (int hh = 0; hh < 8; hh++) {
                float pr = sp[j * 9 + hh];
                acc[hh][0] += pr * vf.x; acc[hh][1] += pr * vf.y;
                acc[hh][2] += pr * vf.z; acc[hh][3] += pr * vf.w;
            }
        }
        __syncthreads();
    }

    // combine per-warp partial accumulators (reuse k_sm: 8192 floats)
    float* st = k_sm;
#pragma unroll
    for (int hh = 0; hh < 8; hh++)
        *(float4*)(st + w * 1024 + hh * DH + l * 4) =
            make_float4(acc[hh][0], acc[hh][1], acc[hh][2], acc[hh][3]);
    __syncthreads();

    int pbase = ((b * KVH + kv) * NSPLIT + split) * 8;
#pragma unroll
    for (int it = 0; it < 4; it++) {
        int d = it * 32 + l;
        float s = 0.f;
#pragma unroll
        for (int ww = 0; ww < 8; ww++) s += st[ww * 1024 + w * DH + d];
        g_pacc[(size_t)(pbase + w) * DH + d] = s;
    }
    if (l == 0) { g_pm[pbase + w] = m_run; g_pl[pbase + w] = l_run; }
}

// Combine splits + fold in the single NEW token (q.k_new, v_new).
// grid (16, 32), block 128.
__global__ void combine_kernel()
{
    int h = blockIdx.x, b = blockIdx.y, d = threadIdx.x;
    int kv = h >> 3, hh = h & 7;

    float qd = g_qkv[b * NQKV + h * DH + d] * SCALE;
    float kn = g_qkv[b * NQKV + 2048 + kv * DH + d];
    float vn = g_qkv[b * NQKV + 2304 + kv * DH + d];

    __shared__ float red[4];
    float ws = warp_sum(qd * kn);
    if ((d & 31) == 0) red[d >> 5] = ws;
    __syncthreads();
    float s_new = red[0] + red[1] + red[2] + red[3];

    int base = ((b * KVH + kv) * NSPLIT) * 8 + hh;
    float ms[NSPLIT], ls[NSPLIT];
    float M = s_new;
#pragma unroll
    for (int s = 0; s < NSPLIT; s++) {
        ms[s] = g_pm[base + s * 8];
        ls[s] = g_pl[base + s * 8];
        M = fmaxf(M, ms[s]);
    }
    float en = __expf(s_new - M);
    float L = en;
    float o = en * vn;
#pragma unroll
    for (int s = 0; s < NSPLIT; s++) {
        float e = __expf(ms[s] - M);
        L += e * ls[s];
        o += e * g_pacc[(size_t)(((b * KVH + kv) * NSPLIT + s) * 8 + hh) * DH + d];
    }
    g_attn[b * (H * DH) + h * DH + d] = o / L;
}

// Output projection partial GEMM: g_attn[32,2048] @ Wo[2048,2048].
// grid (32, 16), block 256.
__global__ __launch_bounds__(256) void o_partial_kernel(const float* __restrict__ Wo)
{
    __shared__ float xs[DCHUNK * 33];
    int t = threadIdx.x;
    int d0 = blockIdx.y * DCHUNK;

#pragma unroll
    for (int k2 = 0; k2 < (DCHUNK * B) / 256; k2++) {
        int idx = t + k2 * 256;
        int d = idx & (DCHUNK - 1), bb = idx >> 7;
        xs[d * 33 + bb] = g_attn[bb * D + d0 + d];
    }
    __syncthreads();

    int colbase = blockIdx.x * 64;
    int cg = t & 15, bg = t >> 4;
    const float* wp = Wo + (size_t)d0 * D + colbase + cg * 4;
    float a00=0,a01=0,a02=0,a03=0, a10=0,a11=0,a12=0,a13=0;

#pragma unroll 4
    for (int dd = 0; dd < DCHUNK; dd++) {
        float4 w4 = *(const float4*)wp; wp += D;
        float x0 = xs[dd * 33 + bg * 2];
        float x1 = xs[dd * 33 + bg * 2 + 1];
        a00 += x0*w4.x; a01 += x0*w4.y; a02 += x0*w4.z; a03 += x0*w4.w;
        a10 += x1*w4.x; a11 += x1*w4.y; a12 += x1*w4.z; a13 += x1*w4.w;
    }

    float* o = g_opart + ((size_t)blockIdx.y * B + bg * 2) * D + colbase + cg * 4;
    *(float4*)o = make_float4(a00,a01,a02,a03);
    *(float4*)(o + D) = make_float4(a10,a11,a12,a13);
}

// grid 256, block 256
__global__ void o_reduce_kernel(float* __restrict__ out)
{
    int idx = blockIdx.x * 256 + threadIdx.x;
    int b = idx / D, c = idx % D;
    float s = 0.f;
#pragma unroll
    for (int ch = 0; ch < NCHUNK; ch++)
        s += g_opart[((size_t)ch * B + b) * D + c];
    out[idx] = s;
}

extern "C" void kernel_launch(void* const* d_in, const int* in_sizes, int n_in,
                              void* d_out, int out_size)
{
    const float* hidden = (const float*)d_in[0];
    const float* cosp   = (const float*)d_in[1];
    const float* sinp   = (const float*)d_in[2];
    const float* past_k = (const float*)d_in[3];
    const float* past_v = (const float*)d_in[4];
    const float* Wq     = (const float*)d_in[5];
    const float* bq     = (const float*)d_in[6];
    const float* Wk     = (const float*)d_in[7];
    const float* bk     = (const float*)d_in[8];
    const float* Wv     = (const float*)d_in[9];
    const float* bv     = (const float*)d_in[10];
    const float* Wo     = (const float*)d_in[11];
    float* out = (float*)d_out;

    cudaFuncSetAttribute(attn_split_kernel,
                         cudaFuncAttributeMaxDynamicSharedMemorySize,
                         ATTN_SMEM_BYTES);

    qkv_partial_kernel<<<dim3(NQKV / 64, NCHUNK), 256>>>(hidden, Wq, Wk, Wv);
    qkv_reduce_rope_kernel<<<B, 512>>>(bq, bk, bv, cosp, sinp);
    attn_split_kernel<<<dim3(NSPLIT, KVH, B), 256, ATTN_SMEM_BYTES>>>(past_k, past_v);
    combine_kernel<<<dim3(H, B), 128>>>();
    o_partial_kernel<<<dim3(D / 64, NCHUNK), 256>>>(Wo);
    o_reduce_kernel<<<(B * D) / 256, 256>>>(out);
}

// round 3
// speedup vs baseline: 1.6825x; 1.1719x over previous
#include <cuda_runtime.h>
#include <cuda_bf16.h>
#include <cstdint>
#include <math_constants.h>

// Problem constants
#define B 32
#define SP 8192
#define D 2048
#define H 16
#define KVH 2
#define DH 128
#define NQKV 2560           // 2048 (q) + 256 (k) + 256 (v)
#define SCALE 0.08838834764831845f  // 1/sqrt(128)

// GEMM tiling
#define DCHUNK 128
#define NCHUNK 16           // D / DCHUNK

// Attention tiling
#define TS 32               // positions per tile
#define NSPLIT 32
#define SCHUNK 256          // SP / NSPLIT
#define NTILES 8            // SCHUNK / TS
#define SPST 12             // score row stride (floats), 48B -> float4-aligned
#define ATTN_SMEM_BYTES ((4*TS*DH + TS*SPST + 8) * 4)

// Scratch (device globals; no allocation allowed)
__device__ float g_qkv_part[NCHUNK * B * NQKV];
__device__ float g_qkv[B * NQKV];
__device__ float g_pacc[B * KVH * NSPLIT * 8 * DH];
__device__ float g_pm[B * KVH * NSPLIT * 8];
__device__ float g_pl[B * KVH * NSPLIT * 8];
__device__ float g_attn[B * H * DH];
__device__ float g_opart[NCHUNK * B * D];

typedef unsigned long long u64;

__device__ __forceinline__ u64 pk2(float lo, float hi) {
    u64 r;
    asm("mov.b64 %0, {%1, %2};" : "=l"(r) : "f"(lo), "f"(hi));
    return r;
}
__device__ __forceinline__ float2 upk2(u64 v) {
    float2 f;
    asm("mov.b64 {%0, %1}, %2;" : "=f"(f.x), "=f"(f.y) : "l"(v));
    return f;
}
__device__ __forceinline__ void fma2(u64& d, u64 a, u64 b) {
    asm("fma.rn.f32x2 %0, %1, %2, %0;" : "+l"(d) : "l"(a), "l"(b));
}
__device__ __forceinline__ void mul2(u64& d, u64 a) {
    asm("mul.rn.f32x2 %0, %0, %1;" : "+l"(d) : "l"(a));
}

__device__ __forceinline__ float warp_sum(float v) {
#pragma unroll
    for (int o = 16; o; o >>= 1) v += __shfl_xor_sync(0xffffffffu, v, o);
    return v;
}
__device__ __forceinline__ float warp_max(float v) {
#pragma unroll
    for (int o = 16; o; o >>= 1) v = fmaxf(v, __shfl_xor_sync(0xffffffffu, v, o));
    return v;
}

// ---------------------------------------------------------------------------
// Fused QKV partial GEMM: X[32,2048] @ {Wq|Wk|Wv} -> partial sums per D-chunk.
// grid (40, 16), block 256.
// ---------------------------------------------------------------------------
__global__ __launch_bounds__(256) void qkv_partial_kernel(
    const float* __restrict__ X,
    const float* __restrict__ Wq, const float* __restrict__ Wk,
    const float* __restrict__ Wv)
{
    __shared__ float xs[DCHUNK * 33];
    int t = threadIdx.x;
    int d0 = blockIdx.y * DCHUNK;

#pragma unroll
    for (int k2 = 0; k2 < (DCHUNK * B) / 256; k2++) {
        int idx = t + k2 * 256;
        int d = idx & (DCHUNK - 1), bb = idx >> 7;
        xs[d * 33 + bb] = X[bb * D + d0 + d];
    }
    __syncthreads();

    int colbase = blockIdx.x * 64;
    const float* W; int Nw, lc;
    if (colbase < 2048)       { W = Wq; Nw = 2048; lc = colbase; }
    else if (colbase < 2304)  { W = Wk; Nw = 256;  lc = colbase - 2048; }
    else                      { W = Wv; Nw = 256;  lc = colbase - 2304; }

    int cg = t & 15;   // col group (4 cols)
    int bg = t >> 4;   // batch group (2 batches)

    const float* wp = W + (size_t)d0 * Nw + lc + cg * 4;
    u64 a0 = 0, a1 = 0, a2 = 0, a3 = 0;

#pragma unroll 8
    for (int dd = 0; dd < DCHUNK; dd++) {
        float4 w4 = *(const float4*)wp; wp += Nw;
        u64 w01 = pk2(w4.x, w4.y), w23 = pk2(w4.z, w4.w);
        u64 x00 = pk2(xs[dd * 33 + bg * 2], xs[dd * 33 + bg * 2]);
        u64 x11 = pk2(xs[dd * 33 + bg * 2 + 1], xs[dd * 33 + bg * 2 + 1]);
        fma2(a0, x00, w01); fma2(a1, x00, w23);
        fma2(a2, x11, w01); fma2(a3, x11, w23);
    }

    float2 r0 = upk2(a0), r1 = upk2(a1), r2 = upk2(a2), r3 = upk2(a3);
    float* o = g_qkv_part + ((size_t)blockIdx.y * B + bg * 2) * NQKV + colbase + cg * 4;
    *(float4*)o = make_float4(r0.x, r0.y, r1.x, r1.y);
    *(float4*)(o + NQKV) = make_float4(r2.x, r2.y, r3.x, r3.y);
}

// Fused: reduce 16 partial chunks + bias, then RoPE on q/k. grid 32, block 512.
__global__ void qkv_reduce_rope_kernel(const float* __restrict__ bq,
                                       const float* __restrict__ bk,
                                       const float* __restrict__ bv,
                                       const float* __restrict__ cosp,
                                       const float* __restrict__ sinp)
{
    __shared__ float buf[NQKV];
    int b = blockIdx.x, t = threadIdx.x;

    for (int c = t; c < NQKV; c += 512) {
        float s;
        if (c < 2048) s = bq[c];
        else if (c < 2304) s = bk[c - 2048];
        else s = bv[c - 2304];
#pragma unroll
        for (int ch = 0; ch < NCHUNK; ch++)
            s += g_qkv_part[((size_t)ch * B + b) * NQKV + c];
        buf[c] = s;
    }
    __syncthreads();

    for (int c = t; c < NQKV; c += 512) {
        float v = buf[c];
        if (c < 2304) {  // q or k head -> RoPE
            int d = c & 127;
            int base = c - d;
            float xp = buf[base + ((d + 64) & 127)];
            float rot = (d < 64) ? -xp : xp;
            v = v * cosp[b * DH + d] + rot * sinp[b * DH + d];
        }
        g_qkv[b * NQKV + c] = v;
    }
}

// ---------------------------------------------------------------------------
// Split-KV flash-decode. grid (32, 2, 32), block 256, occ 2.
// Score phase: K read ONCE from smem; q for 8 heads in regs; 9-shfl
// multi-value butterfly reduction. V phase: f32x2 packed accumulation.
// ---------------------------------------------------------------------------
__global__ __launch_bounds__(256, 2) void attn_split_kernel(
    const float* __restrict__ past_k, const float* __restrict__ past_v)
{
    extern __shared__ float sm[];
    float* k_sm = sm;                    // [2][TS*DH]
    float* v_sm = sm + 2 * TS * DH;      // [2][TS*DH]
    float* sp   = sm + 4 * TS * DH;      // [TS][SPST] scores/probs
    float* f_sm = sp + TS * SPST;        // [8] per-head rescale factors

    int split = blockIdx.x, kv = blockIdx.y, b = blockIdx.z;
    int t = threadIdx.x, w = t >> 5, l = t & 31;

    // q: lane l holds q[h][l*4 .. l*4+3] * scale for all 8 heads
    float4 qh[8];
#pragma unroll
    for (int h = 0; h < 8; h++) {
        float4 q4 = *(const float4*)(g_qkv + b * NQKV + (kv * 8 + h) * DH + l * 4);
        qh[h] = make_float4(q4.x * SCALE, q4.y * SCALE, q4.z * SCALE, q4.w * SCALE);
    }
    float m_run = -CUDART_INF_F, l_run = 0.f;
    u64 acc[8][2] = {};

    const float* kbase = past_k + ((size_t)(b * KVH + kv) * SP + (size_t)split * SCHUNK) * DH;
    const float* vbase = past_v + ((size_t)(b * KVH + kv) * SP + (size_t)split * SCHUNK) * DH;

    uint32_t k_u32 = (uint32_t)__cvta_generic_to_shared(k_sm);
    uint32_t v_u32 = (uint32_t)__cvta_generic_to_shared(v_sm);
    int r = t >> 3, c8 = t & 7;

    auto load_tile = [&](int stage, int tile) {
        const float* kp = kbase + (size_t)tile * TS * DH;
        const float* vp = vbase + (size_t)tile * TS * DH;
        uint32_t ks = k_u32 + stage * TS * DH * 4;
        uint32_t vs = v_u32 + stage * TS * DH * 4;
#pragma unroll
        for (int ii = 0; ii < 4; ii++) {
            int off = r * DH + (c8 + ii * 8) * 4;
            asm volatile("cp.async.cg.shared.global [%0], [%1], 16;\n"
                         :: "r"(ks + off * 4), "l"(kp + off));
            asm volatile("cp.async.cg.shared.global [%0], [%1], 16;\n"
                         :: "r"(vs + off * 4), "l"(vp + off));
        }
        asm volatile("cp.async.commit_group;\n");
    };

    load_tile(0, 0);
    for (int tile = 0; tile < NTILES; tile++) {
        int cur = tile & 1;
        if (tile + 1 < NTILES) {
            load_tile(cur ^ 1, tile + 1);
            asm volatile("cp.async.wait_group 1;\n");
        } else {
            asm volatile("cp.async.wait_group 0;\n");
        }
        __syncthreads();

        const float* kc = k_sm + cur * TS * DH;
        const float* vc = v_sm + cur * TS * DH;

        // scores: warp w -> positions w*4..w*4+3. One LDS.128 per position
        // (full unique 512B row), per-lane partials for all 8 heads, then
        // multi-value butterfly: 9 shfl for all 8 head sums.
#pragma unroll
        for (int jj = 0; jj < 4; jj++) {
            int j = w * 4 + jj;
            float4 kf = *(const float4*)(kc + j * DH + l * 4);
            float v[8];
#pragma unroll
            for (int h = 0; h < 8; h++)
                v[h] = kf.x * qh[h].x + kf.y * qh[h].y
                     + kf.z * qh[h].z + kf.w * qh[h].w;
            // xor 16: halve to 4 values (lo lanes heads 0-3, hi heads 4-7)
#pragma unroll
            for (int i = 0; i < 4; i++) {
                float send = (l & 16) ? v[i] : v[i + 4];
                float recv = __shfl_xor_sync(0xffffffffu, send, 16);
                v[i] = ((l & 16) ? v[i + 4] : v[i]) + recv;
            }
            // xor 8: halve to 2 values
#pragma unroll
            for (int i = 0; i < 2; i++) {
                float send = (l & 8) ? v[i] : v[i + 2];
                float recv = __shfl_xor_sync(0xffffffffu, send, 8);
                v[i] = ((l & 8) ? v[i + 2] : v[i]) + recv;
            }
            // xor 4: halve to 1 value; head = l>>2
            {
                float send = (l & 4) ? v[0] : v[1];
                float recv = __shfl_xor_sync(0xffffffffu, send, 4);
                v[0] = ((l & 4) ? v[1] : v[0]) + recv;
            }
            v[0] += __shfl_xor_sync(0xffffffffu, v[0], 2);
            v[0] += __shfl_xor_sync(0xffffffffu, v[0], 1);
            if ((l & 3) == 0) sp[j * SPST + (l >> 2)] = v[0];
        }
        __syncthreads();

        // online softmax: warp w owns head w (lane = position)
        {
            float sj = sp[l * SPST + w];
            float tm = warp_max(sj);
            float mn = fmaxf(m_run, tm);
            float pw = __expf(sj - mn);
            float su = warp_sum(pw);
            float f  = __expf(m_run - mn);
            l_run = l_run * f + su;
            m_run = mn;
            sp[l * SPST + w] = pw;
            if (l == 0) f_sm[w] = f;
        }
        __syncthreads();

        // rescale accumulators (packed)
#pragma unroll
        for (int hh = 0; hh < 8; hh++) {
            float f = f_sm[hh];
            u64 f2 = pk2(f, f);
            mul2(acc[hh][0], f2); mul2(acc[hh][1], f2);
        }
        // V accumulation: lane owns dims l*4..l*4+3 for all 8 heads (packed)
#pragma unroll
        for (int jj = 0; jj < 4; jj++) {
            int j = w * 4 + jj;
            float4 vf = *(const float4*)(vc + j * DH + l * 4);
            u64 v01 = pk2(vf.x, vf.y), v23 = pk2(vf.z, vf.w);
            float4 pa = *(const float4*)(sp + j * SPST);
            float4 pb = *(const float4*)(sp + j * SPST + 4);
            u64 p;
            p = pk2(pa.x, pa.x); fma2(acc[0][0], p, v01); fma2(acc[0][1], p, v23);
            p = pk2(pa.y, pa.y); fma2(acc[1][0], p, v01); fma2(acc[1][1], p, v23);
            p = pk2(pa.z, pa.z); fma2(acc[2][0], p, v01); fma2(acc[2][1], p, v23);
            p = pk2(pa.w, pa.w); fma2(acc[3][0], p, v01); fma2(acc[3][1], p, v23);
            p = pk2(pb.x, pb.x); fma2(acc[4][0], p, v01); fma2(acc[4][1], p, v23);
            p = pk2(pb.y, pb.y); fma2(acc[5][0], p, v01); fma2(acc[5][1], p, v23);
            p = pk2(pb.z, pb.z); fma2(acc[6][0], p, v01); fma2(acc[6][1], p, v23);
            p = pk2(pb.w, pb.w); fma2(acc[7][0], p, v01); fma2(acc[7][1], p, v23);
        }
        __syncthreads();
    }

    // combine per-warp partial accumulators (reuse k_sm: 8192 floats)
    float* st = k_sm;
#pragma unroll
    for (int hh = 0; hh < 8; hh++) {
        float2 x0 = upk2(acc[hh][0]), x1 = upk2(acc[hh][1]);
        *(float4*)(st + w * 1024 + hh * DH + l * 4) =
            make_float4(x0.x, x0.y, x1.x, x1.y);
    }
    __syncthreads();

    int pbase = ((b * KVH + kv) * NSPLIT + split) * 8;
#pragma unroll
    for (int it = 0; it < 4; it++) {
        int d = it * 32 + l;
        float s = 0.f;
#pragma unroll
        for (int ww = 0; ww < 8; ww++) s += st[ww * 1024 + w * DH + d];
        g_pacc[(size_t)(pbase + w) * DH + d] = s;
    }
    if (l == 0) { g_pm[pbase + w] = m_run; g_pl[pbase + w] = l_run; }
}

// Combine splits + fold in the single NEW token (q.k_new, v_new).
// grid (16, 32), block 128.
__global__ void combine_kernel()
{
    int h = blockIdx.x, b = blockIdx.y, d = threadIdx.x;
    int kv = h >> 3, hh = h & 7;

    float qd = g_qkv[b * NQKV + h * DH + d] * SCALE;
    float kn = g_qkv[b * NQKV + 2048 + kv * DH + d];
    float vn = g_qkv[b * NQKV + 2304 + kv * DH + d];

    __shared__ float red[4];
    float ws = warp_sum(qd * kn);
    if ((d & 31) == 0) red[d >> 5] = ws;
    __syncthreads();
    float s_new = red[0] + red[1] + red[2] + red[3];

    int base = ((b * KVH + kv) * NSPLIT) * 8 + hh;
    float ms[NSPLIT], ls[NSPLIT];
    float M = s_new;
#pragma unroll
    for (int s = 0; s < NSPLIT; s++) {
        ms[s] = g_pm[base + s * 8];
        ls[s] = g_pl[base + s * 8];
        M = fmaxf(M, ms[s]);
    }
    float pv[NSPLIT];
#pragma unroll
    for (int s = 0; s < NSPLIT; s++)
        pv[s] = g_pacc[(size_t)(((b * KVH + kv) * NSPLIT + s) * 8 + hh) * DH + d];

    float en = __expf(s_new - M);
    float L = en;
    float o = en * vn;
#pragma unroll
    for (int s = 0; s < NSPLIT; s++) {
        float e = __expf(ms[s] - M);
        L += e * ls[s];
        o += e * pv[s];
    }
    g_attn[b * (H * DH) + h * DH + d] = o / L;
}

// Output projection partial GEMM: g_attn[32,2048] @ Wo[2048,2048].
// grid (32, 16), block 256.
__global__ __launch_bounds__(256) void o_partial_kernel(const float* __restrict__ Wo)
{
    __shared__ float xs[DCHUNK * 33];
    int t = threadIdx.x;
    int d0 = blockIdx.y * DCHUNK;

#pragma unroll
    for (int k2 = 0; k2 < (DCHUNK * B) / 256; k2++) {
        int idx = t + k2 * 256;
        int d = idx & (DCHUNK - 1), bb = idx >> 7;
        xs[d * 33 + bb] = g_attn[bb * D + d0 + d];
    }
    __syncthreads();

    int colbase = blockIdx.x * 64;
    int cg = t & 15, bg = t >> 4;
    const float* wp = Wo + (size_t)d0 * D + colbase + cg * 4;
    u64 a0 = 0, a1 = 0, a2 = 0, a3 = 0;

#pragma unroll 8
    for (int dd = 0; dd < DCHUNK; dd++) {
        float4 w4 = *(const float4*)wp; wp += D;
        u64 w01 = pk2(w4.x, w4.y), w23 = pk2(w4.z, w4.w);
        u64 x00 = pk2(xs[dd * 33 + bg * 2], xs[dd * 33 + bg * 2]);
        u64 x11 = pk2(xs[dd * 33 + bg * 2 + 1], xs[dd * 33 + bg * 2 + 1]);
        fma2(a0, x00, w01); fma2(a1, x00, w23);
        fma2(a2, x11, w01); fma2(a3, x11, w23);
    }

    float2 r0 = upk2(a0), r1 = upk2(a1), r2 = upk2(a2), r3 = upk2(a3);
    float* o = g_opart + ((size_t)blockIdx.y * B + bg * 2) * D + colbase + cg * 4;
    *(float4*)o = make_float4(r0.x, r0.y, r1.x, r1.y);
    *(float4*)(o + D) = make_float4(r2.x, r2.y, r3.x, r3.y);
}

// grid 256, block 256
__global__ void o_reduce_kernel(float* __restrict__ out)
{
    int idx = blockIdx.x * 256 + threadIdx.x;
    int b = idx / D, c = idx % D;
    float s = 0.f;
#pragma unroll
    for (int ch = 0; ch < NCHUNK; ch++)
        s += g_opart[((size_t)ch * B + b) * D + c];
    out[idx] = s;
}

extern "C" void kernel_launch(void* const* d_in, const int* in_sizes, int n_in,
                              void* d_out, int out_size)
{
    const float* hidden = (const float*)d_in[0];
    const float* cosp   = (const float*)d_in[1];
    const float* sinp   = (const float*)d_in[2];
    const float* past_k = (const float*)d_in[3];
    const float* past_v = (const float*)d_in[4];
    const float* Wq     = (const float*)d_in[5];
    const float* bq     = (const float*)d_in[6];
    const float* Wk     = (const float*)d_in[7];
    const float* bk     = (const float*)d_in[8];
    const float* Wv     = (const float*)d_in[9];
    const float* bv     = (const float*)d_in[10];
    const float* Wo     = (const float*)d_in[11];
    float* out = (float*)d_out;

    cudaFuncSetAttribute(attn_split_kernel,
                         cudaFuncAttributeMaxDynamicSharedMemorySize,
                         ATTN_SMEM_BYTES);

    qkv_partial_kernel<<<dim3(NQKV / 64, NCHUNK), 256>>>(hidden, Wq, Wk, Wv);
    qkv_reduce_rope_kernel<<<B, 512>>>(bq, bk, bv, cosp, sinp);
    attn_split_kernel<<<dim3(NSPLIT, KVH, B), 256, ATTN_SMEM_BYTES>>>(past_k, past_v);
    combine_kernel<<<dim3(H, B), 128>>>();
    o_partial_kernel<<<dim3(D / 64, NCHUNK), 256>>>(Wo);
    o_reduce_kernel<<<(B * D) / 256, 256>>>(out);
}

// round 4
// speedup vs baseline: 1.9962x; 1.1864x over previous
#include <cuda_runtime.h>
#include <cuda_bf16.h>
#include <cstdint>
#include <math_constants.h>

// Problem constants
#define B 32
#define SP 8192
#define D 2048
#define H 16
#define KVH 2
#define DH 128
#define NQKV 2560           // 2048 (q) + 256 (k) + 256 (v)
#define SCALE 0.08838834764831845f  // 1/sqrt(128)

// GEMM tiling
#define DCHUNK 128
#define NCHUNK 16           // D / DCHUNK
#define SR 32               // weight subtile rows (double-buffered)

// Attention tiling
#define TS 32               // positions per tile
#define NSTAGE 3
#define NSPLIT 32
#define SCHUNK 256          // SP / NSPLIT
#define NTILES 8            // SCHUNK / TS
#define SPST 12             // score row stride (floats)
#define ATTN_SMEM_BYTES ((2*NSTAGE*TS*DH + TS*SPST + 8) * 4)

// Scratch (device globals; no allocation allowed)
__device__ float g_qkv_part[NCHUNK * B * NQKV];
__device__ float g_qkv[B * NQKV];
__device__ float g_pacc[B * KVH * NSPLIT * 8 * DH];
__device__ float g_pm[B * KVH * NSPLIT * 8];
__device__ float g_pl[B * KVH * NSPLIT * 8];
__device__ float g_attn[B * H * DH];
__device__ float g_opart[NCHUNK * B * D];

typedef unsigned long long u64;

__device__ __forceinline__ u64 pk2(float lo, float hi) {
    u64 r;
    asm("mov.b64 %0, {%1, %2};" : "=l"(r) : "f"(lo), "f"(hi));
    return r;
}
__device__ __forceinline__ float2 upk2(u64 v) {
    float2 f;
    asm("mov.b64 {%0, %1}, %2;" : "=f"(f.x), "=f"(f.y) : "l"(v));
    return f;
}
__device__ __forceinline__ void fma2(u64& d, u64 a, u64 b) {
    asm("fma.rn.f32x2 %0, %1, %2, %0;" : "+l"(d) : "l"(a), "l"(b));
}
__device__ __forceinline__ void mul2(u64& d, u64 a) {
    asm("mul.rn.f32x2 %0, %0, %1;" : "+l"(d) : "l"(a));
}

__device__ __forceinline__ float warp_sum(float v) {
#pragma unroll
    for (int o = 16; o; o >>= 1) v += __shfl_xor_sync(0xffffffffu, v, o);
    return v;
}
__device__ __forceinline__ float warp_max(float v) {
#pragma unroll
    for (int o = 16; o; o >>= 1) v = fmaxf(v, __shfl_xor_sync(0xffffffffu, v, o));
    return v;
}

// ---------------------------------------------------------------------------
// GEMM body shared by qkv/o projections: weights staged in smem (cp.async,
// double-buffered 32-row subtiles), X tile resident in smem.
// ---------------------------------------------------------------------------
__device__ __forceinline__ void gemm_body(
    const float* __restrict__ Xsrc, int xld,
    const float* __restrict__ W, int Nw, int lc, int d0,
    float* __restrict__ Opart, int old_, int colbase)
{
    __shared__ float xs[DCHUNK * 33];
    __shared__ float ws[2][SR * 64];
    int t = threadIdx.x;

#pragma unroll
    for (int k2 = 0; k2 < (DCHUNK * B) / 256; k2++) {
        int idx = t + k2 * 256;
        int d = idx & (DCHUNK - 1), bb = idx >> 7;
        xs[d * 33 + bb] = Xsrc[bb * xld + d0 + d];
    }

    uint32_t ws_u32 = (uint32_t)__cvta_generic_to_shared(&ws[0][0]);
    auto loadw = [&](int stage, int sub) {
        const float* src = W + (size_t)(d0 + sub * SR) * Nw + lc;
#pragma unroll
        for (int i = 0; i < 2; i++) {
            int idx = t + i * 256;
            int r = idx >> 4, c4 = idx & 15;
            asm volatile("cp.async.cg.shared.global [%0], [%1], 16;\n"
                :: "r"(ws_u32 + (stage * SR * 64 + r * 64 + c4 * 4) * 4),
                   "l"(src + (size_t)r * Nw + c4 * 4));
        }
        asm volatile("cp.async.commit_group;\n");
    };

    int cg = t & 15;   // col group (4 cols)
    int bg = t >> 4;   // batch group (2 batches)
    u64 a0 = 0, a1 = 0, a2 = 0, a3 = 0;

    loadw(0, 0);
#pragma unroll
    for (int s = 0; s < DCHUNK / SR; s++) {
        if (s + 1 < DCHUNK / SR) {
            loadw((s + 1) & 1, s + 1);
            asm volatile("cp.async.wait_group 1;\n");
        } else {
            asm volatile("cp.async.wait_group 0;\n");
        }
        __syncthreads();
        const float* wb = &ws[s & 1][0];
#pragma unroll
        for (int dd = 0; dd < SR; dd++) {
            float4 w4 = *(const float4*)(wb + dd * 64 + cg * 4);
            u64 w01 = pk2(w4.x, w4.y), w23 = pk2(w4.z, w4.w);
            float x0 = xs[(s * SR + dd) * 33 + bg * 2];
            float x1 = xs[(s * SR + dd) * 33 + bg * 2 + 1];
            u64 x00 = pk2(x0, x0), x11 = pk2(x1, x1);
            fma2(a0, x00, w01); fma2(a1, x00, w23);
            fma2(a2, x11, w01); fma2(a3, x11, w23);
        }
        __syncthreads();
    }

    float2 r0 = upk2(a0), r1 = upk2(a1), r2 = upk2(a2), r3 = upk2(a3);
    float* o = Opart + ((size_t)blockIdx.y * B + bg * 2) * old_ + colbase + cg * 4;
    *(float4*)o = make_float4(r0.x, r0.y, r1.x, r1.y);
    *(float4*)(o + old_) = make_float4(r2.x, r2.y, r3.x, r3.y);
}

// grid (40, 16), block 256
__global__ __launch_bounds__(256) void qkv_partial_kernel(
    const float* __restrict__ X,
    const float* __restrict__ Wq, const float* __restrict__ Wk,
    const float* __restrict__ Wv)
{
    int colbase = blockIdx.x * 64;
    const float* W; int Nw, lc;
    if (colbase < 2048)       { W = Wq; Nw = 2048; lc = colbase; }
    else if (colbase < 2304)  { W = Wk; Nw = 256;  lc = colbase - 2048; }
    else                      { W = Wv; Nw = 256;  lc = colbase - 2304; }
    gemm_body(X, D, W, Nw, lc, blockIdx.y * DCHUNK, g_qkv_part, NQKV, colbase);
}

// grid (32, 16), block 256
__global__ __launch_bounds__(256) void o_partial_kernel(const float* __restrict__ Wo)
{
    int colbase = blockIdx.x * 64;
    gemm_body(g_attn, D, Wo, D, colbase, blockIdx.y * DCHUNK, g_opart, D, colbase);
}

// Fused: reduce 16 partial chunks + bias, then RoPE. grid 160 (B*5), block 512.
__global__ void qkv_reduce_rope_kernel(const float* __restrict__ bq,
                                       const float* __restrict__ bk,
                                       const float* __restrict__ bv,
                                       const float* __restrict__ cosp,
                                       const float* __restrict__ sinp)
{
    __shared__ float buf[512];
    int b = blockIdx.x / 5, seg = blockIdx.x % 5;
    int tl = threadIdx.x;
    int c = seg * 512 + tl;

    float s;
    if (c < 2048) s = bq[c];
    else if (c < 2304) s = bk[c - 2048];
    else s = bv[c - 2304];
#pragma unroll
    for (int ch = 0; ch < NCHUNK; ch++)
        s += g_qkv_part[((size_t)ch * B + b) * NQKV + c];
    buf[tl] = s;
    __syncthreads();

    float v = s;
    if (c < 2304) {  // q or k head -> RoPE (heads are 128-aligned within segment)
        int d = c & 127;
        float xp = buf[tl - d + ((d + 64) & 127)];
        float rot = (d < 64) ? -xp : xp;
        v = v * cosp[b * DH + d] + rot * sinp[b * DH + d];
    }
    g_qkv[b * NQKV + c] = v;
}

// ---------------------------------------------------------------------------
// Split-KV flash-decode. grid (32, 2, 32), block 256, occ 2, 3-stage pipeline.
// ---------------------------------------------------------------------------
__global__ __launch_bounds__(256, 2) void attn_split_kernel(
    const float* __restrict__ past_k, const float* __restrict__ past_v)
{
    extern __shared__ float sm[];
    float* k_sm = sm;                          // [NSTAGE][TS*DH]
    float* v_sm = sm + NSTAGE * TS * DH;       // [NSTAGE][TS*DH]
    float* sp   = sm + 2 * NSTAGE * TS * DH;   // [TS][SPST]
    float* f_sm = sp + TS * SPST;              // [8]

    int split = blockIdx.x, kv = blockIdx.y, b = blockIdx.z;
    int t = threadIdx.x, w = t >> 5, l = t & 31;

    // q: lane l holds q[h][l*4 .. l*4+3] * scale for all 8 heads
    float4 qh[8];
#pragma unroll
    for (int h = 0; h < 8; h++) {
        float4 q4 = *(const float4*)(g_qkv + b * NQKV + (kv * 8 + h) * DH + l * 4);
        qh[h] = make_float4(q4.x * SCALE, q4.y * SCALE, q4.z * SCALE, q4.w * SCALE);
    }
    float m_run = -CUDART_INF_F, l_run = 0.f;
    u64 acc[8][2] = {};

    const float* kbase = past_k + ((size_t)(b * KVH + kv) * SP + (size_t)split * SCHUNK) * DH;
    const float* vbase = past_v + ((size_t)(b * KVH + kv) * SP + (size_t)split * SCHUNK) * DH;

    uint32_t k_u32 = (uint32_t)__cvta_generic_to_shared(k_sm);
    uint32_t v_u32 = (uint32_t)__cvta_generic_to_shared(v_sm);
    int r = t >> 3, c8 = t & 7;

    auto load_tile = [&](int stage, int tile) {
        const float* kp = kbase + (size_t)tile * TS * DH;
        const float* vp = vbase + (size_t)tile * TS * DH;
        uint32_t ks = k_u32 + stage * TS * DH * 4;
        uint32_t vs = v_u32 + stage * TS * DH * 4;
#pragma unroll
        for (int ii = 0; ii < 4; ii++) {
            int off = r * DH + (c8 + ii * 8) * 4;
            asm volatile("cp.async.cg.shared.global [%0], [%1], 16;\n"
                         :: "r"(ks + off * 4), "l"(kp + off));
            asm volatile("cp.async.cg.shared.global [%0], [%1], 16;\n"
                         :: "r"(vs + off * 4), "l"(vp + off));
        }
        asm volatile("cp.async.commit_group;\n");
    };

    load_tile(0, 0);
    load_tile(1, 1);
    int stage = 0;
    for (int tile = 0; tile < NTILES; tile++) {
        if (tile + 2 < NTILES) {
            int s2 = stage + 2; if (s2 >= NSTAGE) s2 -= NSTAGE;
            load_tile(s2, tile + 2);
            asm volatile("cp.async.wait_group 2;\n");
        } else if (tile + 1 < NTILES) {
            asm volatile("cp.async.wait_group 1;\n");
        } else {
            asm volatile("cp.async.wait_group 0;\n");
        }
        __syncthreads();

        const float* kc = k_sm + stage * TS * DH;
        const float* vc = v_sm + stage * TS * DH;

        // scores: warp w -> positions w*4..w*4+3; K row read ONCE, multi-value
        // butterfly reduction (9 shfl for 8 head sums).
#pragma unroll
        for (int jj = 0; jj < 4; jj++) {
            int j = w * 4 + jj;
            float4 kf = *(const float4*)(kc + j * DH + l * 4);
            float v[8];
#pragma unroll
            for (int h = 0; h < 8; h++)
                v[h] = kf.x * qh[h].x + kf.y * qh[h].y
                     + kf.z * qh[h].z + kf.w * qh[h].w;
#pragma unroll
            for (int i = 0; i < 4; i++) {
                float send = (l & 16) ? v[i] : v[i + 4];
                float recv = __shfl_xor_sync(0xffffffffu, send, 16);
                v[i] = ((l & 16) ? v[i + 4] : v[i]) + recv;
            }
#pragma unroll
            for (int i = 0; i < 2; i++) {
                float send = (l & 8) ? v[i] : v[i + 2];
                float recv = __shfl_xor_sync(0xffffffffu, send, 8);
                v[i] = ((l & 8) ? v[i + 2] : v[i]) + recv;
            }
            {
                float send = (l & 4) ? v[0] : v[1];
                float recv = __shfl_xor_sync(0xffffffffu, send, 4);
                v[0] = ((l & 4) ? v[1] : v[0]) + recv;
            }
            v[0] += __shfl_xor_sync(0xffffffffu, v[0], 2);
            v[0] += __shfl_xor_sync(0xffffffffu, v[0], 1);
            if ((l & 3) == 0) sp[j * SPST + (l >> 2)] = v[0];
        }
        __syncthreads();

        // online softmax: warp w owns head w (lane = position)
        {
            float sj = sp[l * SPST + w];
            float tm = warp_max(sj);
            float mn = fmaxf(m_run, tm);
            float pw = __expf(sj - mn);
            float su = warp_sum(pw);
            float f  = __expf(m_run - mn);
            l_run = l_run * f + su;
            m_run = mn;
            sp[l * SPST + w] = pw;
            if (l == 0) f_sm[w] = f;
        }
        __syncthreads();

        // rescale accumulators (packed)
#pragma unroll
        for (int hh = 0; hh < 8; hh++) {
            float f = f_sm[hh];
            u64 f2 = pk2(f, f);
            mul2(acc[hh][0], f2); mul2(acc[hh][1], f2);
        }
        // V accumulation (packed)
#pragma unroll
        for (int jj = 0; jj < 4; jj++) {
            int j = w * 4 + jj;
            float4 vf = *(const float4*)(vc + j * DH + l * 4);
            u64 v01 = pk2(vf.x, vf.y), v23 = pk2(vf.z, vf.w);
            float4 pa = *(const float4*)(sp + j * SPST);
            float4 pb = *(const float4*)(sp + j * SPST + 4);
            u64 p;
            p = pk2(pa.x, pa.x); fma2(acc[0][0], p, v01); fma2(acc[0][1], p, v23);
            p = pk2(pa.y, pa.y); fma2(acc[1][0], p, v01); fma2(acc[1][1], p, v23);
            p = pk2(pa.z, pa.z); fma2(acc[2][0], p, v01); fma2(acc[2][1], p, v23);
            p = pk2(pa.w, pa.w); fma2(acc[3][0], p, v01); fma2(acc[3][1], p, v23);
            p = pk2(pb.x, pb.x); fma2(acc[4][0], p, v01); fma2(acc[4][1], p, v23);
            p = pk2(pb.y, pb.y); fma2(acc[5][0], p, v01); fma2(acc[5][1], p, v23);
            p = pk2(pb.z, pb.z); fma2(acc[6][0], p, v01); fma2(acc[6][1], p, v23);
            p = pk2(pb.w, pb.w); fma2(acc[7][0], p, v01); fma2(acc[7][1], p, v23);
        }
        __syncthreads();

        stage++; if (stage >= NSTAGE) stage = 0;
    }

    // combine per-warp partial accumulators (reuse k_sm: 8192+ floats)
    float* st = k_sm;
#pragma unroll
    for (int hh = 0; hh < 8; hh++) {
        float2 x0 = upk2(acc[hh][0]), x1 = upk2(acc[hh][1]);
        *(float4*)(st + w * 1024 + hh * DH + l * 4) =
            make_float4(x0.x, x0.y, x1.x, x1.y);
    }
    __syncthreads();

    int pbase = ((b * KVH + kv) * NSPLIT + split) * 8;
#pragma unroll
    for (int it = 0; it < 4; it++) {
        int d = it * 32 + l;
        float s = 0.f;
#pragma unroll
        for (int ww = 0; ww < 8; ww++) s += st[ww * 1024 + w * DH + d];
        g_pacc[(size_t)(pbase + w) * DH + d] = s;
    }
    if (l == 0) { g_pm[pbase + w] = m_run; g_pl[pbase + w] = l_run; }
}

// Combine: 4 subgroups x 8 splits each + log-sum-exp merge; new token in sg0.
// grid (16, 32), block 512.
__global__ __launch_bounds__(512) void combine_kernel()
{
    __shared__ float red[4];
    __shared__ float obuf[4][130];
    __shared__ float mbuf[4], lbuf[4];

    int h = blockIdx.x, b = blockIdx.y;
    int t = threadIdx.x, sg = t >> 7, d = t & 127;
    int kv = h >> 3, hh = h & 7;

    float qd = g_qkv[b * NQKV + h * DH + d] * SCALE;
    float kn = g_qkv[b * NQKV + 2048 + kv * DH + d];
    float vn = g_qkv[b * NQKV + 2304 + kv * DH + d];

    if (sg == 0) {
        float ws_ = warp_sum(qd * kn);
        if ((t & 31) == 0) red[t >> 5] = ws_;
    }
    __syncthreads();
    float s_new = red[0] + red[1] + red[2] + red[3];

    int base0 = (b * KVH + kv) * NSPLIT;
    float ms[8], ls[8], pv[8];
    float M = (sg == 0) ? s_new : -CUDART_INF_F;
#pragma unroll
    for (int s = 0; s < 8; s++) {
        int spl = sg * 8 + s;
        ms[s] = g_pm[(base0 + spl) * 8 + hh];
        ls[s] = g_pl[(base0 + spl) * 8 + hh];
        pv[s] = g_pacc[(size_t)((base0 + spl) * 8 + hh) * DH + d];
        M = fmaxf(M, ms[s]);
    }
    float L = 0.f, o = 0.f;
    if (sg == 0) {
        float en = __expf(s_new - M);
        L = en; o = en * vn;
    }
#pragma unroll
    for (int s = 0; s < 8; s++) {
        float e = __expf(ms[s] - M);
        L += e * ls[s];
        o += e * pv[s];
    }
    obuf[sg][d] = o;
    if (d == 0) { mbuf[sg] = M; lbuf[sg] = L; }
    __syncthreads();

    if (sg == 0) {
        float Mf = fmaxf(fmaxf(mbuf[0], mbuf[1]), fmaxf(mbuf[2], mbuf[3]));
        float Lf = 0.f, of = 0.f;
#pragma unroll
        for (int g = 0; g < 4; g++) {
            float e = __expf(mbuf[g] - Mf);
            Lf += e * lbuf[g];
            of += e * obuf[g][d];
        }
        g_attn[b * (H * DH) + h * DH + d] = of / Lf;
    }
}

// grid 256, block 256
__global__ void o_reduce_kernel(float* __restrict__ out)
{
    int idx = blockIdx.x * 256 + threadIdx.x;
    int b = idx / D, c = idx % D;
    float s = 0.f;
#pragma unroll
    for (int ch = 0; ch < NCHUNK; ch++)
        s += g_opart[((size_t)ch * B + b) * D + c];
    out[idx] = s;
}

extern "C" void kernel_launch(void* const* d_in, const int* in_sizes, int n_in,
                              void* d_out, int out_size)
{
    const float* hidden = (const float*)d_in[0];
    const float* cosp   = (const float*)d_in[1];
    const float* sinp   = (const float*)d_in[2];
    const float* past_k = (const float*)d_in[3];
    const float* past_v = (const float*)d_in[4];
    const float* Wq     = (const float*)d_in[5];
    const float* bq     = (const float*)d_in[6];
    const float* Wk     = (const float*)d_in[7];
    const float* bk     = (const float*)d_in[8];
    const float* Wv     = (const float*)d_in[9];
    const float* bv     = (const float*)d_in[10];
    const float* Wo     = (const float*)d_in[11];
    float* out = (float*)d_out;

    cudaFuncSetAttribute(attn_split_kernel,
                         cudaFuncAttributeMaxDynamicSharedMemorySize,
                         ATTN_SMEM_BYTES);

    qkv_partial_kernel<<<dim3(NQKV / 64, NCHUNK), 256>>>(hidden, Wq, Wk, Wv);
    qkv_reduce_rope_kernel<<<B * 5, 512>>>(bq, bk, bv, cosp, sinp);
    attn_split_kernel<<<dim3(NSPLIT, KVH, B), 256, ATTN_SMEM_BYTES>>>(past_k, past_v);
    combine_kernel<<<dim3(H, B), 512>>>();
    o_partial_kernel<<<dim3(D / 64, NCHUNK), 256>>>(Wo);
    o_reduce_kernel<<<(B * D) / 256, 256>>>(out);
}